// round 2
// baseline (speedup 1.0000x reference)
#include <cuda_runtime.h>
#include <cuda_bf16.h>
#include <math.h>

// Lowpass EMA scan: out[b,t,u] = (1-s[u])*x[b,t,u] + s[u]*prev
// B=16, T=2048, U=1024. One thread per (b,u) chain; serial over t with
// 8-deep software-pipelined loads (loads are independent of the carry).

#define LP_B 16
#define LP_T 2048
#define LP_U 1024
#define LP_UNROLL 8

__global__ void __launch_bounds__(128, 1)
lowpass_scan_kernel(const float* __restrict__ x,
                    const float* __restrict__ level_var,
                    const float* __restrict__ smoothing_var,
                    float* __restrict__ out)
{
    const int tid = blockIdx.x * blockDim.x + threadIdx.x;   // 0..16383
    const int u = tid & (LP_U - 1);
    const int b = tid >> 10;                                  // /LP_U

    // Per-chain constants
    const float sv = smoothing_var[u];
    const float s  = 1.0f / (1.0f + expf(-sv));
    const float c  = 1.0f - s;
    float level    = level_var[u];

    const float* __restrict__ xp = x   + (size_t)b * LP_T * LP_U + u;
    float*       __restrict__ op = out + (size_t)b * LP_T * LP_U + u;

    // Prime the pipeline: first 8 loads in flight
    float cur[LP_UNROLL];
#pragma unroll
    for (int i = 0; i < LP_UNROLL; i++)
        cur[i] = xp[i * LP_U];

    for (int t = 0; t < LP_T; t += LP_UNROLL) {
        // Issue next batch of loads before consuming current batch
        float nxt[LP_UNROLL];
        if (t + LP_UNROLL < LP_T) {
#pragma unroll
            for (int i = 0; i < LP_UNROLL; i++)
                nxt[i] = xp[(t + LP_UNROLL + i) * LP_U];
        }

        // Serial FMA chain + stores (c*x terms are independent of the carry)
#pragma unroll
        for (int i = 0; i < LP_UNROLL; i++) {
            level = fmaf(s, level, c * cur[i]);
            op[(t + i) * LP_U] = level;
        }

#pragma unroll
        for (int i = 0; i < LP_UNROLL; i++)
            cur[i] = nxt[i];
    }
}

extern "C" void kernel_launch(void* const* d_in, const int* in_sizes, int n_in,
                              void* d_out, int out_size)
{
    const float* x            = (const float*)d_in[0];  // [B,T,U]
    const float* level_var    = (const float*)d_in[1];  // [1,U]
    const float* smoothing    = (const float*)d_in[2];  // [1,U]
    float* out                = (float*)d_out;          // [B,T,U]

    const int total_chains = LP_B * LP_U;               // 16384
    const int threads = 128;
    const int blocks = total_chains / threads;          // 128
    lowpass_scan_kernel<<<blocks, threads>>>(x, level_var, smoothing, out);
}

// round 4
// speedup vs baseline: 2.4797x; 2.4797x over previous
#include <cuda_runtime.h>
#include <cuda_bf16.h>
#include <math.h>

// Lowpass EMA scan: out[b,t,u] = (1-s[u])*x[b,t,u] + s[u]*prev
// B=16, T=2048, U=1024. One thread per (b,u) chain; serial over t.
// 32-deep software-pipelined (double-buffered) loads to build ~16KB/SM
// of reads in flight (4 warps/SM x 32 LDG x 128B) -> saturate HBM.

#define LP_B 16
#define LP_T 2048
#define LP_U 1024
#define LP_UNROLL 32

__global__ void __launch_bounds__(128, 1)
lowpass_scan_kernel(const float* __restrict__ x,
                    const float* __restrict__ level_var,
                    const float* __restrict__ smoothing_var,
                    float* __restrict__ out)
{
    const int tid = blockIdx.x * blockDim.x + threadIdx.x;   // 0..16383
    const int u = tid & (LP_U - 1);
    const int b = tid >> 10;

    const float sv = smoothing_var[u];
    const float s  = 1.0f / (1.0f + expf(-sv));
    const float c  = 1.0f - s;
    float level    = level_var[u];

    const float* __restrict__ xp = x   + (size_t)b * LP_T * LP_U + u;
    float*       __restrict__ op = out + (size_t)b * LP_T * LP_U + u;

    // Prime: first batch of 32 loads in flight
    float cur[LP_UNROLL];
#pragma unroll
    for (int i = 0; i < LP_UNROLL; i++)
        cur[i] = __ldcs(xp + i * LP_U);

    // Main loop: issue next batch, then consume current batch.
    for (int t = 0; t < LP_T - LP_UNROLL; t += LP_UNROLL) {
        float nxt[LP_UNROLL];
#pragma unroll
        for (int i = 0; i < LP_UNROLL; i++)
            nxt[i] = __ldcs(xp + (t + LP_UNROLL + i) * LP_U);

#pragma unroll
        for (int i = 0; i < LP_UNROLL; i++) {
            level = fmaf(s, level, c * cur[i]);
            __stcs(op + (t + i) * LP_U, level);
        }

#pragma unroll
        for (int i = 0; i < LP_UNROLL; i++)
            cur[i] = nxt[i];
    }

    // Epilogue: consume final batch
    {
        const int t = LP_T - LP_UNROLL;
#pragma unroll
        for (int i = 0; i < LP_UNROLL; i++) {
            level = fmaf(s, level, c * cur[i]);
            __stcs(op + (t + i) * LP_U, level);
        }
    }
}

extern "C" void kernel_launch(void* const* d_in, const int* in_sizes, int n_in,
                              void* d_out, int out_size)
{
    const float* x         = (const float*)d_in[0];  // [B,T,U]
    const float* level_var = (const float*)d_in[1];  // [1,U]
    const float* smoothing = (const float*)d_in[2];  // [1,U]
    float* out             = (float*)d_out;          // [B,T,U]

    const int total_chains = LP_B * LP_U;            // 16384
    const int threads = 128;
    const int blocks = total_chains / threads;       // 128
    lowpass_scan_kernel<<<blocks, threads>>>(x, level_var, smoothing, out);
}

// round 5
// speedup vs baseline: 2.9909x; 1.2061x over previous
#include <cuda_runtime.h>
#include <cuda_bf16.h>
#include <math.h>

// Lowpass EMA scan: out[b,t,u] = (1-s[u])*x[b,t,u] + s[u]*prev
// B=16, T=2048, U=1024. One thread per (b,u) chain; serial over t.
// 4-buffer / 3-batch-ahead pipeline: ~96 loads issued ahead of the consume
// point (HW caps at ~55 outstanding/warp), targeting ~25KB/SM in flight
// with only 3.46 warps/SM -> saturate HBM.

#define LP_B 16
#define LP_T 2048
#define LP_U 1024
#define BATCH 32
#define NBATCH (LP_T / BATCH)   // 64

__global__ void __launch_bounds__(128, 1)
lowpass_scan_kernel(const float* __restrict__ x,
                    const float* __restrict__ level_var,
                    const float* __restrict__ smoothing_var,
                    float* __restrict__ out)
{
    const int tid = blockIdx.x * blockDim.x + threadIdx.x;   // 0..16383
    const int u = tid & (LP_U - 1);
    const int b = tid >> 10;

    const float sv = smoothing_var[u];
    const float s  = 1.0f / (1.0f + expf(-sv));
    const float c  = 1.0f - s;
    float level    = level_var[u];

    const float* __restrict__ xp = x   + (size_t)b * LP_T * LP_U + u;
    float*       __restrict__ op = out + (size_t)b * LP_T * LP_U + u;

    float buf[4][BATCH];

    // Prologue: load batches 0,1,2
#pragma unroll
    for (int p = 0; p < 3; p++) {
#pragma unroll
        for (int i = 0; i < BATCH; i++)
            buf[p][i] = __ldcs(xp + (p * BATCH + i) * LP_U);
    }

    // Main loop: 15 iterations x 4 batches. Consume batch bt from buf[j],
    // load batch bt+3 into buf[(j+3)&3].
    for (int it = 0; it < (NBATCH / 4) - 1; it++) {
        const int base = it * 4;
#pragma unroll
        for (int j = 0; j < 4; j++) {
            const int bt = base + j;      // consumed batch: 0..59
            const int lb = bt + 3;        // loaded batch:   3..62
#pragma unroll
            for (int i = 0; i < BATCH; i++)
                buf[(j + 3) & 3][i] = __ldcs(xp + (lb * BATCH + i) * LP_U);
#pragma unroll
            for (int i = 0; i < BATCH; i++) {
                level = fmaf(s, level, c * buf[j][i]);
                __stcs(op + (bt * BATCH + i) * LP_U, level);
            }
        }
    }

    // Epilogue: batches 60..63. Only batch 63 still needs loading (at j=0).
    {
        const int base = NBATCH - 4;      // 60
        // j=0: load batch 63 into buf[3], consume batch 60 (buf[0])
#pragma unroll
        for (int i = 0; i < BATCH; i++)
            buf[3][i] = __ldcs(xp + ((NBATCH - 1) * BATCH + i) * LP_U);
#pragma unroll
        for (int j = 0; j < 4; j++) {
            const int bt = base + j;
#pragma unroll
            for (int i = 0; i < BATCH; i++) {
                level = fmaf(s, level, c * buf[j][i]);
                __stcs(op + (bt * BATCH + i) * LP_U, level);
            }
        }
    }
}

extern "C" void kernel_launch(void* const* d_in, const int* in_sizes, int n_in,
                              void* d_out, int out_size)
{
    const float* x         = (const float*)d_in[0];  // [B,T,U]
    const float* level_var = (const float*)d_in[1];  // [1,U]
    const float* smoothing = (const float*)d_in[2];  // [1,U]
    float* out             = (float*)d_out;          // [B,T,U]

    const int total_chains = LP_B * LP_U;            // 16384
    const int threads = 128;
    const int blocks = total_chains / threads;       // 128
    lowpass_scan_kernel<<<blocks, threads>>>(x, level_var, smoothing, out);
}